// round 6
// baseline (speedup 1.0000x reference)
#include <cuda_runtime.h>
#include <math.h>

#define N_SENT 256
#define BATCH  512
#define SEQ    128
#define DIM    1024
#define LOUT   10331
#define LAT    101
#define NS     (N_SENT*SEQ)   /* 32768 */
#define D2     2048

// ---------------- scratch (device globals, no allocation) ----------------
__device__ float g_xc[NS*DIM];        // 128 MB: elmo @ W_ctx_c^T per sentence
__device__ float g_smen[NS];          // mention scores per (sentence, s)
__device__ float g_final[BATCH*D2];   // [men_repr | ctx_repr]
__device__ float g_mproj[BATCH*DIM];  // men_repr @ W_ctx_m^T
__device__ float g_lat[BATCH*LAT];    // latent_label

__global__ void zero_smen_k() {
    int i = blockIdx.x * blockDim.x + threadIdx.x;
    if (i < NS) g_smen[i] = 0.f;
}

// ------- 128x128x8 register-tiled SGEMM, 2-stage smem pipeline (C = A@B^T) -------
// MODE 0: C = A@B^T
// MODE 2: per-row svec[m] += sum_n wvec[n] * tanh(acc[m,n])   (C never stored)
template<int MODE>
__global__ __launch_bounds__(256)
void sgemm_k(const float* __restrict__ A, int lda,
             const float* __restrict__ B, int ldb,
             float* __restrict__ C, int ldc,
             int M, int N, int K,
             const float* __restrict__ wvec,
             float* __restrict__ svec)
{
    __shared__ __align__(16) float As[2][8][128];
    __shared__ __align__(16) float Bs[2][8][128];
    const int tid = threadIdx.x;
    const int tx = tid & 15, ty = tid >> 4;
    const int m0 = blockIdx.y << 7, n0 = blockIdx.x << 7;

    // per-thread load coords (4 elements each of A-tile and B-tile)
    const int lr[4] = { (tid + 0)   >> 3, (tid + 256) >> 3,
                        (tid + 512) >> 3, (tid + 768) >> 3 };
    const int lc = tid & 7;

    float acc[8][8];
#pragma unroll
    for (int i = 0; i < 8; i++)
#pragma unroll
        for (int j = 0; j < 8; j++) acc[i][j] = 0.f;

    const int ntiles = (K + 7) / 8;

    // prologue: load tile 0 into stage 0
    {
        int gk = lc;
#pragma unroll
        for (int l = 0; l < 4; l++) {
            int gm = m0 + lr[l];
            As[0][lc][lr[l]] = (gm < M && gk < K) ? A[(size_t)gm * lda + gk] : 0.f;
            int gn = n0 + lr[l];
            Bs[0][lc][lr[l]] = (gn < N && gk < K) ? B[(size_t)gn * ldb + gk] : 0.f;
        }
    }
    __syncthreads();

    for (int t = 0; t < ntiles; t++) {
        const int cur = t & 1, nxt = cur ^ 1;
        // issue next tile's global loads first (overlap with compute below)
        if (t + 1 < ntiles) {
            int gk = (t + 1) * 8 + lc;
#pragma unroll
            for (int l = 0; l < 4; l++) {
                int gm = m0 + lr[l];
                As[nxt][lc][lr[l]] = (gm < M && gk < K) ? A[(size_t)gm * lda + gk] : 0.f;
                int gn = n0 + lr[l];
                Bs[nxt][lc][lr[l]] = (gn < N && gk < K) ? B[(size_t)gn * ldb + gk] : 0.f;
            }
        }
#pragma unroll
        for (int kk = 0; kk < 8; kk++) {
            float4 a0 = *reinterpret_cast<const float4*>(&As[cur][kk][ty * 8]);
            float4 a1 = *reinterpret_cast<const float4*>(&As[cur][kk][ty * 8 + 4]);
            float4 b0 = *reinterpret_cast<const float4*>(&Bs[cur][kk][tx * 8]);
            float4 b1 = *reinterpret_cast<const float4*>(&Bs[cur][kk][tx * 8 + 4]);
            float a[8]  = {a0.x, a0.y, a0.z, a0.w, a1.x, a1.y, a1.z, a1.w};
            float bb[8] = {b0.x, b0.y, b0.z, b0.w, b1.x, b1.y, b1.z, b1.w};
#pragma unroll
            for (int i = 0; i < 8; i++)
#pragma unroll
                for (int j = 0; j < 8; j++)
                    acc[i][j] = fmaf(a[i], bb[j], acc[i][j]);
        }
        __syncthreads();
    }

    if constexpr (MODE == 2) {
        __shared__ float red[128][17];
        float wv[8];
#pragma unroll
        for (int j = 0; j < 8; j++) {
            int gn = n0 + tx * 8 + j;
            wv[j] = (gn < N) ? wvec[gn] : 0.f;
        }
#pragma unroll
        for (int i = 0; i < 8; i++) {
            float p = 0.f;
#pragma unroll
            for (int j = 0; j < 8; j++) p += wv[j] * tanhf(acc[i][j]);
            red[ty * 8 + i][tx] = p;
        }
        __syncthreads();
        if (tid < 128) {
            float s = 0.f;
#pragma unroll
            for (int l = 0; l < 16; l++) s += red[tid][l];
            if (m0 + tid < M) atomicAdd(&svec[m0 + tid], s);
        }
    } else {
#pragma unroll
        for (int i = 0; i < 8; i++) {
            int gm = m0 + ty * 8 + i;
            if (gm < M) {
#pragma unroll
                for (int j = 0; j < 8; j++) {
                    int gn = n0 + tx * 8 + j;
                    if (gn < N)
                        C[(size_t)gm * ldc + gn] = acc[i][j];
                }
            }
        }
    }
}

// ---------------- mention attention: softmax + weighted sum --------------
__global__ __launch_bounds__(128)
void men_attn_k(const float* __restrict__ elmo,
                const float* __restrict__ men_mask,
                const int*   __restrict__ gathers)
{
    int b = blockIdx.x, t = threadIdx.x;
    __shared__ float attn[SEQ];
    __shared__ float red[SEQ];
    int g = gathers[b];
    float sc = g_smen[g * SEQ + t] + (1.f - men_mask[b * SEQ + t]) * (-10000.f);
    red[t] = sc; __syncthreads();
#pragma unroll
    for (int st = 64; st; st >>= 1) {
        if (t < st) red[t] = fmaxf(red[t], red[t + st]);
        __syncthreads();
    }
    float mx = red[0]; __syncthreads();
    float e = expf(sc - mx);
    red[t] = e; __syncthreads();
#pragma unroll
    for (int st = 64; st; st >>= 1) {
        if (t < st) red[t] += red[t + st];
        __syncthreads();
    }
    attn[t] = e / red[0];
    __syncthreads();

    const float4* xb = reinterpret_cast<const float4*>(elmo + (size_t)g * SEQ * DIM);
    float4 a0 = {0,0,0,0}, a1 = {0,0,0,0};
    for (int s = 0; s < SEQ; s++) {
        float a = attn[s];
        float4 v0 = xb[s * 256 + t];
        float4 v1 = xb[s * 256 + 128 + t];
        a0.x = fmaf(v0.x, a, a0.x); a0.y = fmaf(v0.y, a, a0.y);
        a0.z = fmaf(v0.z, a, a0.z); a0.w = fmaf(v0.w, a, a0.w);
        a1.x = fmaf(v1.x, a, a1.x); a1.y = fmaf(v1.y, a, a1.y);
        a1.z = fmaf(v1.z, a, a1.z); a1.w = fmaf(v1.w, a, a1.w);
    }
    float4* fr = reinterpret_cast<float4*>(g_final + b * D2);
    fr[t] = a0; fr[128 + t] = a1;
}

// ---------------- context: fused tanh-dot score + softmax + weighted sum --
__global__ __launch_bounds__(256)
void ctx_k(const float* __restrict__ elmo,
           const float* __restrict__ dist,
           const float* __restrict__ ctx_mask,
           const float* __restrict__ wd,
           const float* __restrict__ wo,
           const int*   __restrict__ gathers)
{
    int b = blockIdx.x, t = threadIdx.x;
    int lane = t & 31, w = t >> 5;
    __shared__ float mp[DIM], swd[DIM], swo[DIM];
    __shared__ float score[SEQ];
    __shared__ float red[SEQ];
    for (int i = t; i < DIM; i += 256) {
        mp[i]  = g_mproj[b * DIM + i];
        swd[i] = wd[i];
        swo[i] = wo[i];
    }
    __syncthreads();
    int g = gathers[b];
    for (int s = w; s < SEQ; s += 8) {
        float dv = dist[b * SEQ + s];
        const float* row = g_xc + ((size_t)g * SEQ + s) * DIM;
        float p = 0.f;
        for (int e = lane; e < DIM; e += 32)
            p += swo[e] * tanhf(row[e] + mp[e] + dv * swd[e]);
#pragma unroll
        for (int o = 16; o; o >>= 1) p += __shfl_xor_sync(0xffffffffu, p, o);
        if (lane == 0)
            score[s] = p + (1.f - ctx_mask[b * SEQ + s]) * (-10000.f);
    }
    __syncthreads();
    if (t < 128) red[t] = score[t];
    __syncthreads();
#pragma unroll
    for (int st = 64; st; st >>= 1) {
        if (t < st) red[t] = fmaxf(red[t], red[t + st]);
        __syncthreads();
    }
    float mx = red[0]; __syncthreads();
    if (t < 128) { float e = expf(score[t] - mx); score[t] = e; red[t] = e; }
    __syncthreads();
#pragma unroll
    for (int st = 64; st; st >>= 1) {
        if (t < st) red[t] += red[t + st];
        __syncthreads();
    }
    float inv = 1.f / red[0];
    __syncthreads();
    if (t < 128) score[t] *= inv;
    __syncthreads();

    const float4* xb = reinterpret_cast<const float4*>(elmo + (size_t)g * SEQ * DIM);
    float4 a0 = {0,0,0,0};
    for (int s = 0; s < SEQ; s++) {
        float a = score[s];
        float4 v = xb[s * 256 + t];
        a0.x = fmaf(v.x, a, a0.x); a0.y = fmaf(v.y, a, a0.y);
        a0.z = fmaf(v.z, a, a0.z); a0.w = fmaf(v.w, a, a0.w);
    }
    float4* fr = reinterpret_cast<float4*>(g_final + b * D2 + DIM);
    fr[t] = a0;
}

// ---------------- latent = final @ W_f2l^T (512 x 101) -------------------
__global__ __launch_bounds__(128)
void latent_k(const float* __restrict__ Wf2l)
{
    int b0 = blockIdx.x * 4, t = threadIdx.x;
    int lane = t & 31, w = t >> 5;
    __shared__ float sf[4][D2];
    for (int i = t; i < 4 * D2; i += 128)
        sf[i >> 11][i & 2047] = g_final[(b0 + (i >> 11)) * D2 + (i & 2047)];
    __syncthreads();
    for (int j = w; j < LAT; j += 4) {
        const float* wr = Wf2l + j * D2;
        float a0 = 0.f, a1 = 0.f, a2 = 0.f, a3 = 0.f;
        for (int k = lane; k < D2; k += 32) {
            float v = wr[k];
            a0 = fmaf(v, sf[0][k], a0);
            a1 = fmaf(v, sf[1][k], a1);
            a2 = fmaf(v, sf[2][k], a2);
            a3 = fmaf(v, sf[3][k], a3);
        }
#pragma unroll
        for (int o = 16; o; o >>= 1) {
            a0 += __shfl_xor_sync(0xffffffffu, a0, o);
            a1 += __shfl_xor_sync(0xffffffffu, a1, o);
            a2 += __shfl_xor_sync(0xffffffffu, a2, o);
            a3 += __shfl_xor_sync(0xffffffffu, a3, o);
        }
        if (lane == 0) {
            g_lat[(b0 + 0) * LAT + j] = a0;
            g_lat[(b0 + 1) * LAT + j] = a1;
            g_lat[(b0 + 2) * LAT + j] = a2;
            g_lat[(b0 + 3) * LAT + j] = a3;
        }
    }
}

// ---------------- outputs += latent_scalar * outputs_latent --------------
__global__ __launch_bounds__(256)
void axpy_k(float* __restrict__ out, const float* __restrict__ ol,
            const float* __restrict__ ls_ptr, int n4)
{
    int i = blockIdx.x * blockDim.x + threadIdx.x;
    if (i < n4) {
        float ls = ls_ptr[0];
        float4 o = reinterpret_cast<float4*>(out)[i];
        float4 l = reinterpret_cast<const float4*>(ol)[i];
        o.x = fmaf(ls, l.x, o.x); o.y = fmaf(ls, l.y, o.y);
        o.z = fmaf(ls, l.z, o.z); o.w = fmaf(ls, l.w, o.w);
        reinterpret_cast<float4*>(out)[i] = o;
    }
}

// ---------------- launch ----------------
extern "C" void kernel_launch(void* const* d_in, const int* in_sizes, int n_in,
                              void* d_out, int out_size)
{
    const float* elmo      = (const float*)d_in[0];
    const float* men_mask  = (const float*)d_in[1];
    const float* ctx_mask  = (const float*)d_in[2];
    const float* dist      = (const float*)d_in[3];
    const int*   gathers   = (const int*)  d_in[4];
    const float* W_men_m   = (const float*)d_in[5];
    const float* W_men_o   = (const float*)d_in[6];
    const float* W_ctx_c   = (const float*)d_in[7];
    const float* W_ctx_m   = (const float*)d_in[8];
    const float* w_ctx_d   = (const float*)d_in[9];
    const float* W_ctx_o   = (const float*)d_in[10];
    const float* W_out     = (const float*)d_in[11];
    const float* W_f2l     = (const float*)d_in[12];
    const float* W_l2l     = (const float*)d_in[13];
    const float* lat_scal  = (const float*)d_in[14];

    float* out  = (float*)d_out;               // outputs        [B, L]
    float* out2 = out + (size_t)BATCH * LOUT;  // outputs_latent [B, L]

    float *xc, *smen, *finalp, *mproj, *latp;
    cudaGetSymbolAddress((void**)&xc,     g_xc);
    cudaGetSymbolAddress((void**)&smen,   g_smen);
    cudaGetSymbolAddress((void**)&finalp, g_final);
    cudaGetSymbolAddress((void**)&mproj,  g_mproj);
    cudaGetSymbolAddress((void**)&latp,   g_lat);

    // 1. zero mention scores (MODE-2 epilogue atomically accumulates into them)
    zero_smen_k<<<NS / 256, 256>>>();

    // 2. fused mention-score GEMM (per-sentence, 2x saving vs per-batch):
    //    s_men[n,s] = sum_e W_men_o[e] * tanh( (elmo @ W_men_m^T)[n,s,e] )
    sgemm_k<2><<<dim3(8, 256), 256>>>(elmo, DIM, W_men_m, DIM, nullptr, 0,
                                      NS, DIM, DIM, W_men_o, smen);

    // 3. context projection GEMM (per-sentence): xc = elmo @ W_ctx_c^T
    sgemm_k<0><<<dim3(8, 256), 256>>>(elmo, DIM, W_ctx_c, DIM, xc, DIM,
                                      NS, DIM, DIM, nullptr, nullptr);

    // 4. mention attention -> final[:, :1024]
    men_attn_k<<<BATCH, 128>>>(elmo, men_mask, gathers);

    // 5. men_proj = men_repr @ W_ctx_m^T  (reads first DIM cols of final via lda=D2)
    sgemm_k<0><<<dim3(8, 4), 256>>>(finalp, D2, W_ctx_m, DIM, mproj, DIM,
                                    BATCH, DIM, DIM, nullptr, nullptr);

    // 6. context attention (fused tanh-dot + softmax + weighted sum) -> final[:, 1024:]
    ctx_k<<<BATCH, 256>>>(elmo, dist, ctx_mask, w_ctx_d, W_ctx_o, gathers);

    // 7. latent = final @ W_f2l^T
    latent_k<<<BATCH / 4, 128>>>(W_f2l);

    // 8. outputs_latent = latent @ W_l2l^T   -> out2
    sgemm_k<0><<<dim3((LOUT + 127) / 128, BATCH / 128), 256>>>(
        latp, LAT, W_l2l, LAT, out2, LOUT, BATCH, LOUT, LAT, nullptr, nullptr);

    // 9. outputs = final @ W_out^T           -> out
    sgemm_k<0><<<dim3((LOUT + 127) / 128, BATCH / 128), 256>>>(
        finalp, D2, W_out, D2, out, LOUT, BATCH, LOUT, D2, nullptr, nullptr);

    // 10. outputs += latent_scalar * outputs_latent
    int n4 = (BATCH * LOUT) / 4;
    axpy_k<<<(n4 + 255) / 256, 256>>>(out, out2, lat_scal, n4);
}

// round 7
// speedup vs baseline: 1.0252x; 1.0252x over previous
#include <cuda_runtime.h>
#include <math.h>

#define N_SENT 256
#define BATCH  512
#define SEQ    128
#define DIM    1024
#define LOUT   10331
#define LAT    101
#define NS     (N_SENT*SEQ)   /* 32768 */
#define D2     2048

typedef unsigned long long u64;

// ---- packed f32x2 helpers (sm_103a dual-issue fp32 FMA) ----
__device__ __forceinline__ u64 pack2(float lo, float hi) {
    u64 r; asm("mov.b64 %0, {%1, %2};" : "=l"(r) : "f"(lo), "f"(hi)); return r;
}
__device__ __forceinline__ void unpack2(u64 v, float& lo, float& hi) {
    asm("mov.b64 {%0, %1}, %2;" : "=f"(lo), "=f"(hi) : "l"(v));
}
__device__ __forceinline__ u64 ffma2(u64 a, u64 b, u64 c) {
    u64 d; asm("fma.rn.f32x2 %0, %1, %2, %3;" : "=l"(d) : "l"(a), "l"(b), "l"(c));
    return d;
}

// ---------------- scratch (device globals, no allocation) ----------------
__device__ float g_xc[NS*DIM];        // 128 MB: elmo @ W_ctx_c^T per sentence
__device__ float g_smen[NS];          // mention scores per (sentence, s)
__device__ float g_final[BATCH*D2];   // [men_repr | ctx_repr]
__device__ float g_mproj[BATCH*DIM];  // men_repr @ W_ctx_m^T
__device__ float g_lat[BATCH*LAT];    // latent_label

__global__ void zero_smen_k() {
    int i = blockIdx.x * blockDim.x + threadIdx.x;
    if (i < NS) g_smen[i] = 0.f;
}

// ------- 128x128x8 register-tiled SGEMM, 2-stage smem pipeline, f32x2 core -------
// C = A @ B^T.  MODE 0: store C.
// MODE 2: per-row svec[m] += sum_n wvec[n] * tanh(acc[m,n])   (C never stored)
template<int MODE>
__global__ __launch_bounds__(256)
void sgemm_k(const float* __restrict__ A, int lda,
             const float* __restrict__ B, int ldb,
             float* __restrict__ C, int ldc,
             int M, int N, int K,
             const float* __restrict__ wvec,
             float* __restrict__ svec)
{
    __shared__ __align__(16) float As[2][8][128];
    __shared__ __align__(16) float Bs[2][8][128];
    const int tid = threadIdx.x;
    const int tx = tid & 15, ty = tid >> 4;
    const int m0 = blockIdx.y << 7, n0 = blockIdx.x << 7;

    const int lr[4] = { (tid + 0)   >> 3, (tid + 256) >> 3,
                        (tid + 512) >> 3, (tid + 768) >> 3 };
    const int lc = tid & 7;

    // packed accumulators: acc2[i][j] holds columns (2j, 2j+1) of row i
    u64 acc2[8][4];
#pragma unroll
    for (int i = 0; i < 8; i++)
#pragma unroll
        for (int j = 0; j < 4; j++) acc2[i][j] = pack2(0.f, 0.f);

    const int ntiles = (K + 7) / 8;

    // prologue: tile 0 -> stage 0
    {
        int gk = lc;
#pragma unroll
        for (int l = 0; l < 4; l++) {
            int gm = m0 + lr[l];
            As[0][lc][lr[l]] = (gm < M && gk < K) ? A[(size_t)gm * lda + gk] : 0.f;
            int gn = n0 + lr[l];
            Bs[0][lc][lr[l]] = (gn < N && gk < K) ? B[(size_t)gn * ldb + gk] : 0.f;
        }
    }
    __syncthreads();

    for (int t = 0; t < ntiles; t++) {
        const int cur = t & 1, nxt = cur ^ 1;
        if (t + 1 < ntiles) {
            int gk = (t + 1) * 8 + lc;
#pragma unroll
            for (int l = 0; l < 4; l++) {
                int gm = m0 + lr[l];
                As[nxt][lc][lr[l]] = (gm < M && gk < K) ? A[(size_t)gm * lda + gk] : 0.f;
                int gn = n0 + lr[l];
                Bs[nxt][lc][lr[l]] = (gn < N && gk < K) ? B[(size_t)gn * ldb + gk] : 0.f;
            }
        }
#pragma unroll
        for (int kk = 0; kk < 8; kk++) {
            float4 a0 = *reinterpret_cast<const float4*>(&As[cur][kk][ty * 8]);
            float4 a1 = *reinterpret_cast<const float4*>(&As[cur][kk][ty * 8 + 4]);
            float4 b0 = *reinterpret_cast<const float4*>(&Bs[cur][kk][tx * 8]);
            float4 b1 = *reinterpret_cast<const float4*>(&Bs[cur][kk][tx * 8 + 4]);
            u64 bp[4] = { pack2(b0.x, b0.y), pack2(b0.z, b0.w),
                          pack2(b1.x, b1.y), pack2(b1.z, b1.w) };
            float av[8] = {a0.x, a0.y, a0.z, a0.w, a1.x, a1.y, a1.z, a1.w};
#pragma unroll
            for (int i = 0; i < 8; i++) {
                u64 ad = pack2(av[i], av[i]);
#pragma unroll
                for (int j = 0; j < 4; j++)
                    acc2[i][j] = ffma2(ad, bp[j], acc2[i][j]);
            }
        }
        __syncthreads();
    }

    // unpack accumulators
    float acc[8][8];
#pragma unroll
    for (int i = 0; i < 8; i++)
#pragma unroll
        for (int j = 0; j < 4; j++)
            unpack2(acc2[i][j], acc[i][2 * j], acc[i][2 * j + 1]);

    if constexpr (MODE == 2) {
        __shared__ float red[128][17];
        float wv[8];
#pragma unroll
        for (int j = 0; j < 8; j++) {
            int gn = n0 + tx * 8 + j;
            wv[j] = (gn < N) ? wvec[gn] : 0.f;
        }
#pragma unroll
        for (int i = 0; i < 8; i++) {
            float p = 0.f;
#pragma unroll
            for (int j = 0; j < 8; j++) p += wv[j] * tanhf(acc[i][j]);
            red[ty * 8 + i][tx] = p;
        }
        __syncthreads();
        if (tid < 128) {
            float s = 0.f;
#pragma unroll
            for (int l = 0; l < 16; l++) s += red[tid][l];
            if (m0 + tid < M) atomicAdd(&svec[m0 + tid], s);
        }
    } else {
#pragma unroll
        for (int i = 0; i < 8; i++) {
            int gm = m0 + ty * 8 + i;
            if (gm < M) {
#pragma unroll
                for (int j = 0; j < 8; j++) {
                    int gn = n0 + tx * 8 + j;
                    if (gn < N)
                        C[(size_t)gm * ldc + gn] = acc[i][j];
                }
            }
        }
    }
}

// ---------------- mention attention: softmax + weighted sum --------------
__global__ __launch_bounds__(128)
void men_attn_k(const float* __restrict__ elmo,
                const float* __restrict__ men_mask,
                const int*   __restrict__ gathers)
{
    int b = blockIdx.x, t = threadIdx.x;
    __shared__ float attn[SEQ];
    __shared__ float red[SEQ];
    int g = gathers[b];
    float sc = g_smen[g * SEQ + t] + (1.f - men_mask[b * SEQ + t]) * (-10000.f);
    red[t] = sc; __syncthreads();
#pragma unroll
    for (int st = 64; st; st >>= 1) {
        if (t < st) red[t] = fmaxf(red[t], red[t + st]);
        __syncthreads();
    }
    float mx = red[0]; __syncthreads();
    float e = expf(sc - mx);
    red[t] = e; __syncthreads();
#pragma unroll
    for (int st = 64; st; st >>= 1) {
        if (t < st) red[t] += red[t + st];
        __syncthreads();
    }
    attn[t] = e / red[0];
    __syncthreads();

    const float4* xb = reinterpret_cast<const float4*>(elmo + (size_t)g * SEQ * DIM);
    float4 a0 = {0,0,0,0}, a1 = {0,0,0,0};
    for (int s = 0; s < SEQ; s++) {
        float a = attn[s];
        float4 v0 = xb[s * 256 + t];
        float4 v1 = xb[s * 256 + 128 + t];
        a0.x = fmaf(v0.x, a, a0.x); a0.y = fmaf(v0.y, a, a0.y);
        a0.z = fmaf(v0.z, a, a0.z); a0.w = fmaf(v0.w, a, a0.w);
        a1.x = fmaf(v1.x, a, a1.x); a1.y = fmaf(v1.y, a, a1.y);
        a1.z = fmaf(v1.z, a, a1.z); a1.w = fmaf(v1.w, a, a1.w);
    }
    float4* fr = reinterpret_cast<float4*>(g_final + b * D2);
    fr[t] = a0; fr[128 + t] = a1;
}

// ---------------- context: fused tanh-dot score + softmax + weighted sum --
__global__ __launch_bounds__(256)
void ctx_k(const float* __restrict__ elmo,
           const float* __restrict__ dist,
           const float* __restrict__ ctx_mask,
           const float* __restrict__ wd,
           const float* __restrict__ wo,
           const int*   __restrict__ gathers)
{
    int b = blockIdx.x, t = threadIdx.x;
    int lane = t & 31, w = t >> 5;
    __shared__ float mp[DIM], swd[DIM], swo[DIM];
    __shared__ float score[SEQ];
    __shared__ float red[SEQ];
    for (int i = t; i < DIM; i += 256) {
        mp[i]  = g_mproj[b * DIM + i];
        swd[i] = wd[i];
        swo[i] = wo[i];
    }
    __syncthreads();
    int g = gathers[b];
    for (int s = w; s < SEQ; s += 8) {
        float dv = dist[b * SEQ + s];
        const float* row = g_xc + ((size_t)g * SEQ + s) * DIM;
        float p = 0.f;
        for (int e = lane; e < DIM; e += 32)
            p += swo[e] * tanhf(row[e] + mp[e] + dv * swd[e]);
#pragma unroll
        for (int o = 16; o; o >>= 1) p += __shfl_xor_sync(0xffffffffu, p, o);
        if (lane == 0)
            score[s] = p + (1.f - ctx_mask[b * SEQ + s]) * (-10000.f);
    }
    __syncthreads();
    if (t < 128) red[t] = score[t];
    __syncthreads();
#pragma unroll
    for (int st = 64; st; st >>= 1) {
        if (t < st) red[t] = fmaxf(red[t], red[t + st]);
        __syncthreads();
    }
    float mx = red[0]; __syncthreads();
    if (t < 128) { float e = expf(score[t] - mx); score[t] = e; red[t] = e; }
    __syncthreads();
#pragma unroll
    for (int st = 64; st; st >>= 1) {
        if (t < st) red[t] += red[t + st];
        __syncthreads();
    }
    float inv = 1.f / red[0];
    __syncthreads();
    if (t < 128) score[t] *= inv;
    __syncthreads();

    const float4* xb = reinterpret_cast<const float4*>(elmo + (size_t)g * SEQ * DIM);
    float4 a0 = {0,0,0,0};
    for (int s = 0; s < SEQ; s++) {
        float a = score[s];
        float4 v = xb[s * 256 + t];
        a0.x = fmaf(v.x, a, a0.x); a0.y = fmaf(v.y, a, a0.y);
        a0.z = fmaf(v.z, a, a0.z); a0.w = fmaf(v.w, a, a0.w);
    }
    float4* fr = reinterpret_cast<float4*>(g_final + b * D2 + DIM);
    fr[t] = a0;
}

// ---------------- latent = final @ W_f2l^T (512 x 101) -------------------
__global__ __launch_bounds__(128)
void latent_k(const float* __restrict__ Wf2l)
{
    int b0 = blockIdx.x * 4, t = threadIdx.x;
    int lane = t & 31, w = t >> 5;
    __shared__ float sf[4][D2];
    for (int i = t; i < 4 * D2; i += 128)
        sf[i >> 11][i & 2047] = g_final[(b0 + (i >> 11)) * D2 + (i & 2047)];
    __syncthreads();
    for (int j = w; j < LAT; j += 4) {
        const float* wr = Wf2l + j * D2;
        float a0 = 0.f, a1 = 0.f, a2 = 0.f, a3 = 0.f;
        for (int k = lane; k < D2; k += 32) {
            float v = wr[k];
            a0 = fmaf(v, sf[0][k], a0);
            a1 = fmaf(v, sf[1][k], a1);
            a2 = fmaf(v, sf[2][k], a2);
            a3 = fmaf(v, sf[3][k], a3);
        }
#pragma unroll
        for (int o = 16; o; o >>= 1) {
            a0 += __shfl_xor_sync(0xffffffffu, a0, o);
            a1 += __shfl_xor_sync(0xffffffffu, a1, o);
            a2 += __shfl_xor_sync(0xffffffffu, a2, o);
            a3 += __shfl_xor_sync(0xffffffffu, a3, o);
        }
        if (lane == 0) {
            g_lat[(b0 + 0) * LAT + j] = a0;
            g_lat[(b0 + 1) * LAT + j] = a1;
            g_lat[(b0 + 2) * LAT + j] = a2;
            g_lat[(b0 + 3) * LAT + j] = a3;
        }
    }
}

// ---------------- outputs += latent_scalar * outputs_latent --------------
__global__ __launch_bounds__(256)
void axpy_k(float* __restrict__ out, const float* __restrict__ ol,
            const float* __restrict__ ls_ptr, int n4)
{
    int i = blockIdx.x * blockDim.x + threadIdx.x;
    if (i < n4) {
        float ls = ls_ptr[0];
        float4 o = reinterpret_cast<float4*>(out)[i];
        float4 l = reinterpret_cast<const float4*>(ol)[i];
        o.x = fmaf(ls, l.x, o.x); o.y = fmaf(ls, l.y, o.y);
        o.z = fmaf(ls, l.z, o.z); o.w = fmaf(ls, l.w, o.w);
        reinterpret_cast<float4*>(out)[i] = o;
    }
}

// ---------------- launch ----------------
extern "C" void kernel_launch(void* const* d_in, const int* in_sizes, int n_in,
                              void* d_out, int out_size)
{
    const float* elmo      = (const float*)d_in[0];
    const float* men_mask  = (const float*)d_in[1];
    const float* ctx_mask  = (const float*)d_in[2];
    const float* dist      = (const float*)d_in[3];
    const int*   gathers   = (const int*)  d_in[4];
    const float* W_men_m   = (const float*)d_in[5];
    const float* W_men_o   = (const float*)d_in[6];
    const float* W_ctx_c   = (const float*)d_in[7];
    const float* W_ctx_m   = (const float*)d_in[8];
    const float* w_ctx_d   = (const float*)d_in[9];
    const float* W_ctx_o   = (const float*)d_in[10];
    const float* W_out     = (const float*)d_in[11];
    const float* W_f2l     = (const float*)d_in[12];
    const float* W_l2l     = (const float*)d_in[13];
    const float* lat_scal  = (const float*)d_in[14];

    float* out  = (float*)d_out;               // outputs        [B, L]
    float* out2 = out + (size_t)BATCH * LOUT;  // outputs_latent [B, L]

    float *xc, *smen, *finalp, *mproj, *latp;
    cudaGetSymbolAddress((void**)&xc,     g_xc);
    cudaGetSymbolAddress((void**)&smen,   g_smen);
    cudaGetSymbolAddress((void**)&finalp, g_final);
    cudaGetSymbolAddress((void**)&mproj,  g_mproj);
    cudaGetSymbolAddress((void**)&latp,   g_lat);

    // 1. zero mention scores (MODE-2 epilogue atomically accumulates into them)
    zero_smen_k<<<NS / 256, 256>>>();

    // 2. fused mention-score GEMM (per-sentence, 2x saving vs per-batch):
    //    s_men[n,s] = sum_e W_men_o[e] * tanh( (elmo @ W_men_m^T)[n,s,e] )
    sgemm_k<2><<<dim3(8, 256), 256>>>(elmo, DIM, W_men_m, DIM, nullptr, 0,
                                      NS, DIM, DIM, W_men_o, smen);

    // 3. context projection GEMM (per-sentence): xc = elmo @ W_ctx_c^T
    sgemm_k<0><<<dim3(8, 256), 256>>>(elmo, DIM, W_ctx_c, DIM, xc, DIM,
                                      NS, DIM, DIM, nullptr, nullptr);

    // 4. mention attention -> final[:, :1024]
    men_attn_k<<<BATCH, 128>>>(elmo, men_mask, gathers);

    // 5. men_proj = men_repr @ W_ctx_m^T  (reads first DIM cols of final via lda=D2)
    sgemm_k<0><<<dim3(8, 4), 256>>>(finalp, D2, W_ctx_m, DIM, mproj, DIM,
                                    BATCH, DIM, DIM, nullptr, nullptr);

    // 6. context attention (fused tanh-dot + softmax + weighted sum) -> final[:, 1024:]
    ctx_k<<<BATCH, 256>>>(elmo, dist, ctx_mask, w_ctx_d, W_ctx_o, gathers);

    // 7. latent = final @ W_f2l^T
    latent_k<<<BATCH / 4, 128>>>(W_f2l);

    // 8. outputs_latent = latent @ W_l2l^T   -> out2
    sgemm_k<0><<<dim3((LOUT + 127) / 128, BATCH / 128), 256>>>(
        latp, LAT, W_l2l, LAT, out2, LOUT, BATCH, LOUT, LAT, nullptr, nullptr);

    // 9. outputs = final @ W_out^T           -> out
    sgemm_k<0><<<dim3((LOUT + 127) / 128, BATCH / 128), 256>>>(
        finalp, D2, W_out, D2, out, LOUT, BATCH, LOUT, D2, nullptr, nullptr);

    // 10. outputs += latent_scalar * outputs_latent
    int n4 = (BATCH * LOUT) / 4;
    axpy_k<<<(n4 + 255) / 256, 256>>>(out, out2, lat_scal, n4);
}